// round 3
// baseline (speedup 1.0000x reference)
#include <cuda_runtime.h>
#include <cuda_bf16.h>
#include <cstdint>

// ---------------- scratch (device globals; no allocation allowed) ----------
__device__ float g_adj[32 * 256 * 256];        // binary adjacency (diag forced)
__device__ float g_invrow[32 * 256];           // 1 / rowsum
__device__ float g_G[32 * 4 * 256 * 256];      // F @ Wl

// ---------------- threefry2x32, key = (0, 42) ------------------------------
__device__ __forceinline__ void tf2x32(unsigned x0, unsigned x1,
                                       unsigned& o0, unsigned& o1) {
    const unsigned k0 = 0u, k1 = 42u, k2 = 0x1BD11BF0u;  // 0x1BD11BDA ^ 0 ^ 42
    x0 += k0; x1 += k1;
#define TFR(r) { x0 += x1; x1 = __funnelshift_l(x1, x1, (r)); x1 ^= x0; }
    TFR(13) TFR(15) TFR(26) TFR(6)   x0 += k1; x1 += k2 + 1u;
    TFR(17) TFR(29) TFR(16) TFR(24)  x0 += k2; x1 += k0 + 2u;
    TFR(13) TFR(15) TFR(26) TFR(6)   x0 += k0; x1 += k1 + 3u;
    TFR(17) TFR(29) TFR(16) TFR(24)  x0 += k1; x1 += k2 + 4u;
    TFR(13) TFR(15) TFR(26) TFR(6)   x0 += k2; x1 += k0 + 5u;
#undef TFR
    o0 = x0; o1 = x1;
}

// gumbel sample at flattened element index i of the (32,65536,2) uniform draw.
// JAX >= 0.4.36 default: threefry_partitionable=True. For 32-bit random bits:
//   counter = uint64 flat index i -> (hi=0, lo=i); bits = out0 ^ out1.
__device__ __forceinline__ float gumbel_at(unsigned i) {
    unsigned o0, o1;
    tf2x32(0u, i, o0, o1);
    unsigned bits = o0 ^ o1;
    float f = __uint_as_float((bits >> 9) | 0x3F800000u) - 1.0f;  // [0,1)
    float u = fmaxf(1e-10f, f + 1e-10f);
    return -logf(-logf(u));
}

__device__ __forceinline__ float gelu_exact(float x) {
    return 0.5f * x * (1.0f + erff(x * 0.7071067811865476f));
}

// ---------------- kernel 1: corr tile + MLP + gumbel -> binary adjacency ---
// grid (S/32, S/32, B), block 256. 32x32 output tile, 2x2 per thread.
__global__ void adj_kernel(const float* __restrict__ fm,
                           const float* __restrict__ W1, const float* __restrict__ B1,
                           const float* __restrict__ W2, const float* __restrict__ B2,
                           const float* __restrict__ W3, const float* __restrict__ B3) {
    const int b  = blockIdx.z;
    const int s0 = blockIdx.y * 32;
    const int t0 = blockIdx.x * 32;
    const float* base = fm + (size_t)b * 65536;

    __shared__ float As[32][65];
    __shared__ float Bs[32][65];
    __shared__ float w1[16], bb1[16], w2[128], bb2[8], w3[16], bb3[2];

    const int tid = threadIdx.x;
    if (tid < 16) { w1[tid] = W1[tid]; bb1[tid] = B1[tid]; w3[tid] = W3[tid]; }
    if (tid >= 32 && tid < 160) w2[tid - 32] = W2[tid - 32];
    if (tid >= 160 && tid < 168) bb2[tid - 160] = B2[tid - 160];
    if (tid >= 168 && tid < 170) bb3[tid - 168] = B3[tid - 168];

    const int ty = tid >> 4, tx = tid & 15;
    float acc[2][2] = {{0.f, 0.f}, {0.f, 0.f}};

    // vectorized loads: 32x64 tile = 512 float4 per buffer, 2 per thread
    const int vr  = tid >> 4;          // row 0..15 (x2 iterations -> 32 rows)
    const int vc4 = tid & 15;          // float4 column 0..15 (64 floats)

    for (int kk = 0; kk < 256; kk += 64) {
        __syncthreads();
#pragma unroll
        for (int it = 0; it < 2; it++) {
            int r = vr + it * 16;
            float4 a = *(const float4*)(base + (s0 + r) * 256 + kk + vc4 * 4);
            float4 c = *(const float4*)(base + (t0 + r) * 256 + kk + vc4 * 4);
            As[r][vc4 * 4 + 0] = a.x; As[r][vc4 * 4 + 1] = a.y;
            As[r][vc4 * 4 + 2] = a.z; As[r][vc4 * 4 + 3] = a.w;
            Bs[r][vc4 * 4 + 0] = c.x; Bs[r][vc4 * 4 + 1] = c.y;
            Bs[r][vc4 * 4 + 2] = c.z; Bs[r][vc4 * 4 + 3] = c.w;
        }
        __syncthreads();
#pragma unroll
        for (int k = 0; k < 64; k++) {
            float a0 = As[ty * 2][k],     a1 = As[ty * 2 + 1][k];
            float c0 = Bs[tx * 2][k],     c1 = Bs[tx * 2 + 1][k];
            acc[0][0] = fmaf(a0, c0, acc[0][0]);
            acc[0][1] = fmaf(a0, c1, acc[0][1]);
            acc[1][0] = fmaf(a1, c0, acc[1][0]);
            acc[1][1] = fmaf(a1, c1, acc[1][1]);
        }
    }

#pragma unroll
    for (int i = 0; i < 2; i++) {
#pragma unroll
        for (int j = 0; j < 2; j++) {
            int s = s0 + ty * 2 + i;
            int t = t0 + tx * 2 + j;
            float c = acc[i][j];
            // tiny MLP 1->16->8->2 (exact-erf GELU)
            float h1[16];
#pragma unroll
            for (int q = 0; q < 16; q++) h1[q] = gelu_exact(fmaf(c, w1[q], bb1[q]));
            float l0 = bb3[0], l1 = bb3[1];
#pragma unroll
            for (int k2 = 0; k2 < 8; k2++) {
                float s2 = bb2[k2];
#pragma unroll
                for (int q = 0; q < 16; q++) s2 = fmaf(h1[q], w2[q * 8 + k2], s2);
                float h2 = gelu_exact(s2);
                l0 = fmaf(h2, w3[k2 * 2 + 0], l0);
                l1 = fmaf(h2, w3[k2 * 2 + 1], l1);
            }
            // gumbel-hard: argmax(logits + g); log_softmax shift cancels
            unsigned p  = (unsigned)(s * 256 + t);
            unsigned i0 = (unsigned)b * 131072u + p * 2u;
            float g0 = gumbel_at(i0);
            float g1 = gumbel_at(i0 + 1u);
            float a = (l0 + g0 >= l1 + g1) ? 1.0f : 0.0f;
            if (s == t) a = 1.0f;  // a + (1-a)*I
            g_adj[(size_t)b * 65536 + p] = a;
        }
    }
}

// ---------------- kernel 2: per-row inverse sum -----------------------------
__global__ void rowsum_kernel() {
    int row = blockIdx.x;  // b*256 + s
    float v = g_adj[(size_t)row * 256 + threadIdx.x];
    __shared__ float red[8];
#pragma unroll
    for (int o = 16; o; o >>= 1) v += __shfl_down_sync(0xFFFFFFFFu, v, o);
    if ((threadIdx.x & 31) == 0) red[threadIdx.x >> 5] = v;
    __syncthreads();
    if (threadIdx.x == 0) {
        float s = 0.f;
#pragma unroll
        for (int i = 0; i < 8; i++) s += red[i];
        g_invrow[row] = 1.0f / s;
    }
}

// ---------------- kernel 3: G = F @ Wl  (M=32768, K=256, N=256) -------------
// 64x64 tile, BK=16, 256 threads, 4x4 per thread. float4 loads.
__global__ void gemm_fwl(const float* __restrict__ F, const float* __restrict__ Wl) {
    const int m0 = blockIdx.y * 64, n0 = blockIdx.x * 64;
    __shared__ float As[64][17];
    __shared__ float Bs[16][68];
    const int tid = threadIdx.x;
    const int ty = tid >> 4, tx = tid & 15;
    // A tile: 64x16 = 256 float4 (one per thread)
    const int ar  = tid >> 2, ac4 = tid & 3;
    // B tile: 16x64 = 256 float4 (one per thread)
    const int br  = tid >> 4, bc4 = tid & 15;
    float acc[4][4] = {};

    for (int k0 = 0; k0 < 256; k0 += 16) {
        __syncthreads();
        {
            float4 a = *(const float4*)(F + (size_t)(m0 + ar) * 256 + k0 + ac4 * 4);
            As[ar][ac4 * 4 + 0] = a.x; As[ar][ac4 * 4 + 1] = a.y;
            As[ar][ac4 * 4 + 2] = a.z; As[ar][ac4 * 4 + 3] = a.w;
            float4 bv = *(const float4*)(Wl + (size_t)(k0 + br) * 256 + n0 + bc4 * 4);
            Bs[br][bc4 * 4 + 0] = bv.x; Bs[br][bc4 * 4 + 1] = bv.y;
            Bs[br][bc4 * 4 + 2] = bv.z; Bs[br][bc4 * 4 + 3] = bv.w;
        }
        __syncthreads();
#pragma unroll
        for (int k = 0; k < 16; k++) {
            float ra[4], rb[4];
#pragma unroll
            for (int i = 0; i < 4; i++) { ra[i] = As[ty * 4 + i][k]; rb[i] = Bs[k][tx * 4 + i]; }
#pragma unroll
            for (int i = 0; i < 4; i++)
#pragma unroll
                for (int j = 0; j < 4; j++) acc[i][j] = fmaf(ra[i], rb[j], acc[i][j]);
        }
    }
#pragma unroll
    for (int i = 0; i < 4; i++)
#pragma unroll
        for (int j = 0; j < 4; j++)
            g_G[(size_t)(m0 + ty * 4 + i) * 256 + n0 + tx * 4 + j] = acc[i][j];
}

// ---------------- kernel 4: out = (A/rowsum) @ G + bl  per (b,c) ------------
// grid (N/64, S/64, B*C); same tiling as above.
__global__ void gemm_out(float* __restrict__ out, const float* __restrict__ bl) {
    const int bz = blockIdx.z;           // b*4 + c
    const int b  = bz >> 2;
    const int m0 = blockIdx.y * 64, n0 = blockIdx.x * 64;
    __shared__ float As[64][17];
    __shared__ float Bs[16][68];
    const int tid = threadIdx.x;
    const int ty = tid >> 4, tx = tid & 15;
    const int ar  = tid >> 2, ac4 = tid & 3;
    const int br  = tid >> 4, bc4 = tid & 15;
    float acc[4][4] = {};

    const float* Abase = g_adj + (size_t)b * 65536;
    const float* inv   = g_invrow + b * 256;
    const float* Gbase = g_G + (size_t)bz * 65536;

    const float invA = inv[m0 + ar];

    for (int k0 = 0; k0 < 256; k0 += 16) {
        __syncthreads();
        {
            float4 a = *(const float4*)(Abase + (m0 + ar) * 256 + k0 + ac4 * 4);
            As[ar][ac4 * 4 + 0] = a.x * invA; As[ar][ac4 * 4 + 1] = a.y * invA;
            As[ar][ac4 * 4 + 2] = a.z * invA; As[ar][ac4 * 4 + 3] = a.w * invA;
            float4 bv = *(const float4*)(Gbase + (k0 + br) * 256 + n0 + bc4 * 4);
            Bs[br][bc4 * 4 + 0] = bv.x; Bs[br][bc4 * 4 + 1] = bv.y;
            Bs[br][bc4 * 4 + 2] = bv.z; Bs[br][bc4 * 4 + 3] = bv.w;
        }
        __syncthreads();
#pragma unroll
        for (int k = 0; k < 16; k++) {
            float ra[4], rb[4];
#pragma unroll
            for (int i = 0; i < 4; i++) { ra[i] = As[ty * 4 + i][k]; rb[i] = Bs[k][tx * 4 + i]; }
#pragma unroll
            for (int i = 0; i < 4; i++)
#pragma unroll
                for (int j = 0; j < 4; j++) acc[i][j] = fmaf(ra[i], rb[j], acc[i][j]);
        }
    }
#pragma unroll
    for (int i = 0; i < 4; i++) {
#pragma unroll
        for (int j = 0; j < 4; j++) {
            int n = n0 + tx * 4 + j;
            out[(size_t)(bz * 256 + m0 + ty * 4 + i) * 256 + n] = acc[i][j] + bl[n];
        }
    }
}

// ---------------- launch -----------------------------------------------------
extern "C" void kernel_launch(void* const* d_in, const int* in_sizes, int n_in,
                              void* d_out, int out_size) {
    const float* features = (const float*)d_in[0];  // [32,4,256,256]
    const float* fmean    = (const float*)d_in[1];  // [32,256,256]
    const float* W1 = (const float*)d_in[2];
    const float* B1 = (const float*)d_in[3];
    const float* W2 = (const float*)d_in[4];
    const float* B2 = (const float*)d_in[5];
    const float* W3 = (const float*)d_in[6];
    const float* B3 = (const float*)d_in[7];
    const float* Wl = (const float*)d_in[8];
    const float* bl = (const float*)d_in[9];
    float* out = (float*)d_out;

    adj_kernel<<<dim3(8, 8, 32), 256>>>(fmean, W1, B1, W2, B2, W3, B3);
    rowsum_kernel<<<32 * 256, 256>>>();
    gemm_fwl<<<dim3(4, 512), 256>>>(features, Wl);
    gemm_out<<<dim3(4, 4, 128), 256>>>(out, bl);
}